// round 5
// baseline (speedup 1.0000x reference)
#include <cuda_runtime.h>
#include <cuda_bf16.h>
#include <math.h>

// RotationalConv2D v5 — GB300 sm_103a
// 1 patch/thread (quad g-lanes split 16 channels), FFMA2 over CHANNEL pairs:
// acc[f] u64 = (even-ch partial, odd-ch partial). W staged in smem as
// 16B-aligned u64 channel-pairs, rows padded to 34 u64 (272B) so the four
// g-lane rows hit disjoint bank groups ({0,32,64,96} mod 128) -> conflict-free
// LDS.128. 64 accumulator regs -> 4 blocks/SM at 128 threads.

#define HDIM 128
#define CCH 16
#define FOUT 32
#define KK 5
#define HO 124
#define WO 124
#define NP (4 * HO * WO)     // 61504 = 1922 * 32
#define TPB 128
#define ROWU 34              // u64 per W row (32 f-pairs + 2 pad) = 272B

typedef unsigned long long u64;

__device__ __forceinline__ u64 pk2(float lo, float hi) {
    u64 d; asm("mov.b64 %0, {%1, %2};" : "=l"(d) : "f"(lo), "f"(hi)); return d;
}
__device__ __forceinline__ void upk2(float& lo, float& hi, u64 v) {
    asm("mov.b64 {%0, %1}, %2;" : "=f"(lo), "=f"(hi) : "l"(v));
}
__device__ __forceinline__ u64 ffma2(u64 a, u64 b, u64 c) {
    u64 d; asm("fma.rn.f32x2 %0, %1, %2, %3;" : "=l"(d) : "l"(a), "l"(b), "l"(c)); return d;
}

__global__ void __launch_bounds__(TPB, 4)
rotconv5_kernel(const float* __restrict__ in,
                const float* __restrict__ Wg,
                const float* __restrict__ bias,
                float* __restrict__ out)
{
    extern __shared__ float sm[];    // Ws rows: [(j*4+gq)*2+cp][ROWU u64] = 54400 B

    // --- stage W: row (j,gq,cp) slot f = u64 pair (W[f,j,c0], W[f,j,c0+1]),
    //     c0 = gq*4 + cp*2 ---
    for (int i = threadIdx.x; i < 25 * 4 * 2 * 32 * 2; i += TPB) {
        const int half = i & 1;
        const int f    = (i >> 1) & 31;
        const int cp   = (i >> 6) & 1;
        const int gq   = (i >> 7) & 3;
        const int j    = i >> 9;
        sm[((j * 8 + gq * 2 + cp) * ROWU + f) * 2 + half] =
            Wg[f * 400 + j * 16 + gq * 4 + cp * 2 + half];
    }
    __syncthreads();

    const int tid = threadIdx.x;
    const int pp  = tid >> 2;               // 0..31
    const int g   = tid & 3;
    const int P   = blockIdx.x * 32 + pp;   // grid exact, no tail

    const int b   = P / (HO * WO);
    const int rem = P - b * (HO * WO);
    const int ho  = rem / WO;
    const int wo  = rem - ho * WO;
    const float* pbase = in + ((b * HDIM + ho) * HDIM + wo) * CCH;

    // --- intensity / centroid / angle (lane's 4 channels, quad butterfly) ---
    float tot = 0.f, sr = 0.f, sc = 0.f;
    #pragma unroll
    for (int r = 0; r < KK; r++) {
        #pragma unroll
        for (int cl = 0; cl < KK; cl++) {
            float4 v = *reinterpret_cast<const float4*>(pbase + (r * HDIM + cl) * CCH + g * 4);
            float s = v.x + v.y + v.z + v.w;
            tot += s;
            sr  += s * (float)r;
            sc  += s * (float)cl;
        }
    }
    tot += __shfl_xor_sync(0xffffffffu, tot, 1);
    tot += __shfl_xor_sync(0xffffffffu, tot, 2);
    sr  += __shfl_xor_sync(0xffffffffu, sr, 1);
    sr  += __shfl_xor_sync(0xffffffffu, sr, 2);
    sc  += __shfl_xor_sync(0xffffffffu, sc, 1);
    sc  += __shfl_xor_sync(0xffffffffu, sc, 2);

    tot += 1e-7f;
    const float cr   = sr / tot;
    const float ccen = sc / tot;
    const float m    = (float)(KK - 1) * 0.5f;
    const float ang  = atan2f(cr - m, ccen - m + 1e-7f);
    const float co   = __cosf(ang);
    const float si   = __sinf(ang);
    const float km1  = (float)(KK - 1);
    const float xo   = (km1 - (co * km1 - si * km1)) * 0.5f;
    const float yo   = (km1 - (si * km1 + co * km1)) * 0.5f;
    const float scale = 1.0f / (1.0f + 1e-7f);

    u64 acc[FOUT];
    #pragma unroll
    for (int f = 0; f < FOUT; f++) acc[f] = 0ull;

    const u64* wsu = reinterpret_cast<const u64*>(sm);

    // --- main loop over 25 target positions ---
    #pragma unroll 1
    for (int jy = 0; jy < KK; jy++) {
        #pragma unroll 1
        for (int jx = 0; jx < KK; jx++) {
            const float gx = (float)jx;
            const float gy = (float)jy;
            const float sx  = (co * gx - si * gy + xo) * scale;
            const float sy  = (si * gx + co * gy + yo) * scale;
            const float x0f = floorf(sx);
            const float y0f = floorf(sy);
            const float wx  = sx - x0f;
            const float wy  = sy - y0f;
            const int   x0  = (int)x0f;
            const int   y0  = (int)y0f;
            const float tw[4] = { (1.f - wx) * (1.f - wy),
                                  wx * (1.f - wy),
                                  (1.f - wx) * wy,
                                  wx * wy };
            float a0 = 0.f, a1 = 0.f, a2 = 0.f, a3 = 0.f;
            #pragma unroll
            for (int t = 0; t < 4; t++) {
                const int xi = x0 + (t & 1);
                const int yi = y0 + (t >> 1);
                if (xi >= 0 && xi < KK && yi >= 0 && yi < KK) {
                    const float4 v = *reinterpret_cast<const float4*>(
                        pbase + (yi * HDIM + xi) * CCH + g * 4);
                    const float w = tw[t];
                    a0 += w * v.x;
                    a1 += w * v.y;
                    a2 += w * v.z;
                    a3 += w * v.w;
                }
            }
            const u64 rp0 = pk2(a0, a1);     // channels c0, c0+1 (cp=0)
            const u64 rp1 = pk2(a2, a3);     // channels c0+2, c0+3 (cp=1)

            // --- GEMM: W pairs straight from smem, FFMA2 = 2 MACs/instr ---
            const int j = jy * KK + jx;
            const ulonglong2* w0p =
                reinterpret_cast<const ulonglong2*>(wsu + (j * 8 + g * 2) * ROWU);
            const ulonglong2* w1p =
                reinterpret_cast<const ulonglong2*>(wsu + (j * 8 + g * 2 + 1) * ROWU);
            #pragma unroll
            for (int q = 0; q < 16; q++) {
                const ulonglong2 wa = w0p[q];
                acc[2 * q]     = ffma2(wa.x, rp0, acc[2 * q]);
                acc[2 * q + 1] = ffma2(wa.y, rp0, acc[2 * q + 1]);
            }
            #pragma unroll
            for (int q = 0; q < 16; q++) {
                const ulonglong2 wb = w1p[q];
                acc[2 * q]     = ffma2(wb.x, rp1, acc[2 * q]);
                acc[2 * q + 1] = ffma2(wb.y, rp1, acc[2 * q + 1]);
            }
        }
    }

    // --- finalize: hi+lo, quad butterfly over g, store lane's f-slice ---
    float vals[FOUT];
    #pragma unroll
    for (int f = 0; f < FOUT; f++) {
        float lo, hi;
        upk2(lo, hi, acc[f]);
        float s = lo + hi;
        s += __shfl_xor_sync(0xffffffffu, s, 1);
        s += __shfl_xor_sync(0xffffffffu, s, 2);
        vals[f] = s;
    }

    float* op = out + P * FOUT + g * 8;
    #pragma unroll
    for (int k = 0; k < 2; k++) {
        const float4 bv = *reinterpret_cast<const float4*>(bias + g * 8 + k * 4);
        float4 o;
        o.x = vals[g * 8 + k * 4 + 0] + bv.x;
        o.y = vals[g * 8 + k * 4 + 1] + bv.y;
        o.z = vals[g * 8 + k * 4 + 2] + bv.z;
        o.w = vals[g * 8 + k * 4 + 3] + bv.w;
        *reinterpret_cast<float4*>(op + k * 4) = o;
    }
}

extern "C" void kernel_launch(void* const* d_in, const int* in_sizes, int n_in,
                              void* d_out, int out_size)
{
    const float* in   = (const float*)d_in[0];   // [4,128,128,16]
    const float* Wg   = (const float*)d_in[1];   // [32,5,5,16]
    const float* bias = (const float*)d_in[2];   // [32]
    float* out = (float*)d_out;                  // [4,124,124,32]

    const int smem = 25 * 8 * ROWU * 8;          // 54400 B
    cudaFuncSetAttribute(rotconv5_kernel,
                         cudaFuncAttributeMaxDynamicSharedMemorySize, smem);

    const int nblocks = NP / 32;                 // 1922 exact
    rotconv5_kernel<<<nblocks, TPB, smem>>>(in, Wg, bias, out);
}

// round 6
// speedup vs baseline: 1.3116x; 1.3116x over previous
#include <cuda_runtime.h>
#include <cuda_bf16.h>
#include <math.h>

// RotationalConv2D v6 — GB300 sm_103a
// 2 patches/thread, quad channel-split, f-pair FFMA2 accumulators (64 regs).
// W in smem as (j,c) rows of 16 u64 f-pairs = 128B rows (LDS.128-aligned),
// column-rotated by 32B*g so g-lanes hit disjoint bank groups {0,32,64,96}.

#define HDIM 128
#define CCH 16
#define FOUT 32
#define KK 5
#define HO 124
#define WO 124
#define NP (4 * HO * WO)     // 61504 = 961 * 64
#define TPB 128

typedef unsigned long long u64;

__device__ __forceinline__ u64 pk2(float lo, float hi) {
    u64 d; asm("mov.b64 %0, {%1, %2};" : "=l"(d) : "f"(lo), "f"(hi)); return d;
}
__device__ __forceinline__ void upk2(float& lo, float& hi, u64 v) {
    asm("mov.b64 {%0, %1}, %2;" : "=f"(lo), "=f"(hi) : "l"(v));
}
__device__ __forceinline__ u64 ffma2(u64 a, u64 b, u64 c) {
    u64 d; asm("fma.rn.f32x2 %0, %1, %2, %3;" : "=l"(d) : "l"(a), "l"(b), "l"(c)); return d;
}

__global__ void __launch_bounds__(TPB, 4)
rotconv6_kernel(const float* __restrict__ in,
                const float* __restrict__ Wg,
                const float* __restrict__ bias,
                float* __restrict__ out)
{
    extern __shared__ float sm[];   // 25*16 rows * 16 u64 = 51200 B

    // --- stage W: row (j,c), logical u64 slot fp holds (W[2fp],W[2fp+1]) at
    //     physical slot (fp + 4*(c>>2)) & 15  (32B rotation per g-group) ---
    for (int i = threadIdx.x; i < 25 * 16 * 32; i += TPB) {
        const int half = i & 1;
        const int fp   = (i >> 1) & 15;
        const int c    = (i >> 5) & 15;
        const int j    = i >> 9;
        const int phys = (fp + 4 * (c >> 2)) & 15;
        sm[((j * 16 + c) * 16 + phys) * 2 + half] =
            Wg[(2 * fp + half) * 400 + j * 16 + c];
    }
    __syncthreads();

    const int tid  = threadIdx.x;
    const int pp   = tid >> 2;          // 0..31
    const int g    = tid & 3;
    const int base = blockIdx.x * 64;

    int   poff[2];
    float co[2], si[2], xo[2], yo[2];

    #pragma unroll
    for (int u = 0; u < 2; u++) {
        const int P   = base + pp + 32 * u;     // grid exact
        const int b   = P / (HO * WO);
        const int rem = P - b * (HO * WO);
        const int ho  = rem / WO;
        const int wo  = rem - ho * WO;
        poff[u] = ((b * HDIM + ho) * HDIM + wo) * CCH;
        const float* pbase = in + poff[u];

        float tot = 0.f, sr = 0.f, sc = 0.f;
        #pragma unroll
        for (int r = 0; r < KK; r++) {
            #pragma unroll
            for (int cl = 0; cl < KK; cl++) {
                float4 v = *reinterpret_cast<const float4*>(pbase + (r * HDIM + cl) * CCH + g * 4);
                float s = v.x + v.y + v.z + v.w;
                tot += s;
                sr  += s * (float)r;
                sc  += s * (float)cl;
            }
        }
        tot += __shfl_xor_sync(0xffffffffu, tot, 1);
        tot += __shfl_xor_sync(0xffffffffu, tot, 2);
        sr  += __shfl_xor_sync(0xffffffffu, sr, 1);
        sr  += __shfl_xor_sync(0xffffffffu, sr, 2);
        sc  += __shfl_xor_sync(0xffffffffu, sc, 1);
        sc  += __shfl_xor_sync(0xffffffffu, sc, 2);

        tot += 1e-7f;
        const float cr   = sr / tot;
        const float ccen = sc / tot;
        const float m    = (float)(KK - 1) * 0.5f;
        const float ang  = atan2f(cr - m, ccen - m + 1e-7f);
        const float c_   = __cosf(ang);
        const float s_   = __sinf(ang);
        const float km1  = (float)(KK - 1);
        co[u] = c_;
        si[u] = s_;
        xo[u] = (km1 - (c_ * km1 - s_ * km1)) * 0.5f;
        yo[u] = (km1 - (s_ * km1 + c_ * km1)) * 0.5f;
    }

    const float scale = 1.0f / (1.0f + 1e-7f);

    u64 accA[16], accB[16];
    #pragma unroll
    for (int fp = 0; fp < 16; fp++) { accA[fp] = 0ull; accB[fp] = 0ull; }

    const u64* wsu = reinterpret_cast<const u64*>(sm);
    const int  rot4g = 4 * g;           // column rotation in u64 units

    // --- main loop over 25 target positions ---
    #pragma unroll 1
    for (int jy = 0; jy < KK; jy++) {
        #pragma unroll 1
        for (int jx = 0; jx < KK; jx++) {
            const float gx = (float)jx;
            const float gy = (float)jy;

            float rotv[2][4];
            #pragma unroll
            for (int u = 0; u < 2; u++) {
                const float sx  = (co[u] * gx - si[u] * gy + xo[u]) * scale;
                const float sy  = (si[u] * gx + co[u] * gy + yo[u]) * scale;
                const float x0f = floorf(sx);
                const float y0f = floorf(sy);
                const float wx  = sx - x0f;
                const float wy  = sy - y0f;
                const int   x0  = (int)x0f;
                const int   y0  = (int)y0f;
                const float tw[4] = { (1.f - wx) * (1.f - wy),
                                      wx * (1.f - wy),
                                      (1.f - wx) * wy,
                                      wx * wy };
                float a0 = 0.f, a1 = 0.f, a2 = 0.f, a3 = 0.f;
                #pragma unroll
                for (int t = 0; t < 4; t++) {
                    const int xi = x0 + (t & 1);
                    const int yi = y0 + (t >> 1);
                    if (xi >= 0 && xi < KK && yi >= 0 && yi < KK) {
                        const float4 v = *reinterpret_cast<const float4*>(
                            in + poff[u] + (yi * HDIM + xi) * CCH + g * 4);
                        const float w = tw[t];
                        a0 += w * v.x;
                        a1 += w * v.y;
                        a2 += w * v.z;
                        a3 += w * v.w;
                    }
                }
                rotv[u][0] = a0; rotv[u][1] = a1;
                rotv[u][2] = a2; rotv[u][3] = a3;
            }

            // --- GEMM: 8 LDS.128 per channel, FFMA2 = 2 MACs ---
            const int j = jy * KK + jx;
            #pragma unroll
            for (int ci = 0; ci < 4; ci++) {
                const u64 ra = pk2(rotv[0][ci], rotv[0][ci]);
                const u64 rb = pk2(rotv[1][ci], rotv[1][ci]);
                const u64* row = wsu + (j * 16 + rot4g + ci) * 16;
                #pragma unroll
                for (int qq = 0; qq < 8; qq++) {
                    const int ph = (2 * qq + rot4g) & 15;     // rotated, even -> no wrap
                    const ulonglong2 wa = *reinterpret_cast<const ulonglong2*>(row + ph);
                    accA[2 * qq]     = ffma2(wa.x, ra, accA[2 * qq]);
                    accB[2 * qq]     = ffma2(wa.x, rb, accB[2 * qq]);
                    accA[2 * qq + 1] = ffma2(wa.y, ra, accA[2 * qq + 1]);
                    accB[2 * qq + 1] = ffma2(wa.y, rb, accB[2 * qq + 1]);
                }
            }
        }
    }

    // --- quad butterfly over g (u64 shfl = 2x SHFL), then store f-slice ---
    #pragma unroll
    for (int fp = 0; fp < 16; fp++) {
        u64 v = accA[fp];
        v += 0;  // keep as bits; butterfly must add FLOAT pairs:
    }
    // butterfly in float space: unpack, reduce both halves, repack conceptually
    float redA[16][2], redB[16][2];
    #pragma unroll
    for (int fp = 0; fp < 16; fp++) {
        float lo, hi;
        upk2(lo, hi, accA[fp]);
        lo += __shfl_xor_sync(0xffffffffu, lo, 1);
        lo += __shfl_xor_sync(0xffffffffu, lo, 2);
        hi += __shfl_xor_sync(0xffffffffu, hi, 1);
        hi += __shfl_xor_sync(0xffffffffu, hi, 2);
        redA[fp][0] = lo; redA[fp][1] = hi;
        upk2(lo, hi, accB[fp]);
        lo += __shfl_xor_sync(0xffffffffu, lo, 1);
        lo += __shfl_xor_sync(0xffffffffu, lo, 2);
        hi += __shfl_xor_sync(0xffffffffu, hi, 1);
        hi += __shfl_xor_sync(0xffffffffu, hi, 2);
        redB[fp][0] = lo; redB[fp][1] = hi;
    }

    // lane stores filters 8g..8g+7 (= fp 4g..4g+3) for both patches
    const float4 bv0 = *reinterpret_cast<const float4*>(bias + g * 8);
    const float4 bv1 = *reinterpret_cast<const float4*>(bias + g * 8 + 4);
    #pragma unroll
    for (int u = 0; u < 2; u++) {
        const int P = base + pp + 32 * u;
        float* op = out + P * FOUT + g * 8;
        float4 o0, o1;
        if (u == 0) {
            o0.x = redA[4 * g + 0][0] + bv0.x;  o0.y = redA[4 * g + 0][1] + bv0.y;
            o0.z = redA[4 * g + 1][0] + bv0.z;  o0.w = redA[4 * g + 1][1] + bv0.w;
            o1.x = redA[4 * g + 2][0] + bv1.x;  o1.y = redA[4 * g + 2][1] + bv1.y;
            o1.z = redA[4 * g + 3][0] + bv1.z;  o1.w = redA[4 * g + 3][1] + bv1.w;
        } else {
            o0.x = redB[4 * g + 0][0] + bv0.x;  o0.y = redB[4 * g + 0][1] + bv0.y;
            o0.z = redB[4 * g + 1][0] + bv0.z;  o0.w = redB[4 * g + 1][1] + bv0.w;
            o1.x = redB[4 * g + 2][0] + bv1.x;  o1.y = redB[4 * g + 2][1] + bv1.y;
            o1.z = redB[4 * g + 3][0] + bv1.z;  o1.w = redB[4 * g + 3][1] + bv1.w;
        }
        *reinterpret_cast<float4*>(op)     = o0;
        *reinterpret_cast<float4*>(op + 4) = o1;
    }
}

extern "C" void kernel_launch(void* const* d_in, const int* in_sizes, int n_in,
                              void* d_out, int out_size)
{
    const float* in   = (const float*)d_in[0];   // [4,128,128,16]
    const float* Wg   = (const float*)d_in[1];   // [32,5,5,16]
    const float* bias = (const float*)d_in[2];   // [32]
    float* out = (float*)d_out;                  // [4,124,124,32]

    const int smem = 25 * 16 * 16 * 8;           // 51200 B
    cudaFuncSetAttribute(rotconv6_kernel,
                         cudaFuncAttributeMaxDynamicSharedMemorySize, smem);

    const int nblocks = NP / 64;                 // 961 exact
    rotconv6_kernel<<<nblocks, TPB, smem>>>(in, Wg, bias, out);
}

// round 8
// speedup vs baseline: 2.6788x; 2.0425x over previous
#include <cuda_runtime.h>
#include <cuda_bf16.h>
#include <math.h>
#include <cstdint>

// RotationalConv2D v8 — GB300 sm_103a — warp-level tf32 mma.sync GEMM
// Warp = 16-patch tile. Lane t: q=t&3, row=t>>2; owns channels 4q..4q+3 of
// patches row and row+8. k-permutation (kpos q+4i <-> channel 4q+i) makes the
// bilinear float4 land directly in mma.sync A-fragment registers. W staged
// once as tf32 per-lane B-fragments in smem (LDS.64 per mma).

#define HDIM 128
#define CCH 16
#define FOUT 32
#define KK 5
#define HO 124
#define WO 124
#define NP (4 * HO * WO)     // 61504 = 961 * 64
#define TPB 128

__device__ __forceinline__ uint32_t f2tf32(float x) {
    uint32_t r;
    asm("cvt.rn.tf32.f32 %0, %1;" : "=r"(r) : "f"(x));
    return r;
}

__device__ __forceinline__ void mma_tf32(float* c,
                                         uint32_t a0, uint32_t a1,
                                         uint32_t a2, uint32_t a3,
                                         uint32_t b0, uint32_t b1) {
    asm volatile(
        "mma.sync.aligned.m16n8k8.row.col.f32.tf32.tf32.f32 "
        "{%0,%1,%2,%3}, {%4,%5,%6,%7}, {%8,%9}, {%0,%1,%2,%3};"
        : "+f"(c[0]), "+f"(c[1]), "+f"(c[2]), "+f"(c[3])
        : "r"(a0), "r"(a1), "r"(a2), "r"(a3), "r"(b0), "r"(b1));
}

__global__ void __launch_bounds__(TPB, 4)
rotconv8_kernel(const float* __restrict__ in,
                const float* __restrict__ Wg,
                const float* __restrict__ bias,
                float* __restrict__ out)
{
    extern __shared__ uint32_t smw[];   // Bfrag[25][2][4][32][2] tf32 = 51200 B

    const int tid  = threadIdx.x;
    const int wid  = tid >> 5;
    const int lane = tid & 31;

    // --- stage W as per-lane B fragments (tf32) ---
    // idx -> [j][ks][nt][t][r]; value = W[nt*8 + t/4][j*16 + 4*(t%4) + 2*ks + r]
    for (int i = tid; i < 25 * 2 * 4 * 32 * 2; i += TPB) {
        const int r  = i & 1;
        const int t  = (i >> 1) & 31;
        const int nt = (i >> 6) & 3;
        const int ks = (i >> 8) & 1;
        const int j  = i >> 9;
        smw[i] = f2tf32(Wg[(nt * 8 + (t >> 2)) * 400 + j * 16 + 4 * (t & 3) + 2 * ks + r]);
    }
    __syncthreads();

    const int q   = lane & 3;           // k-group / channel-group
    const int row = lane >> 2;          // patch row within tile (0..7)
    const int tb  = blockIdx.x * 64 + wid * 16;   // warp tile base (exact grid)

    // --- per-patch setup: patches tb+row and tb+row+8 ---
    const float* pbase[2];
    float co[2], si[2], xo[2], yo[2];

    #pragma unroll
    for (int u = 0; u < 2; u++) {
        const int P   = tb + row + 8 * u;
        const int b   = P / (HO * WO);
        const int rem = P - b * (HO * WO);
        const int ho  = rem / WO;
        const int wo  = rem - ho * WO;
        const float* pb = in + ((b * HDIM + ho) * HDIM + wo) * CCH;
        pbase[u] = pb;

        float tot = 0.f, sr = 0.f, sc = 0.f;
        #pragma unroll
        for (int r = 0; r < KK; r++) {
            #pragma unroll
            for (int cl = 0; cl < KK; cl++) {
                float4 v = *reinterpret_cast<const float4*>(pb + (r * HDIM + cl) * CCH + q * 4);
                float s = v.x + v.y + v.z + v.w;
                tot += s;
                sr  += s * (float)r;
                sc  += s * (float)cl;
            }
        }
        // the 4 lanes of a patch are consecutive (row fixed, q varies)
        tot += __shfl_xor_sync(0xffffffffu, tot, 1);
        tot += __shfl_xor_sync(0xffffffffu, tot, 2);
        sr  += __shfl_xor_sync(0xffffffffu, sr, 1);
        sr  += __shfl_xor_sync(0xffffffffu, sr, 2);
        sc  += __shfl_xor_sync(0xffffffffu, sc, 1);
        sc  += __shfl_xor_sync(0xffffffffu, sc, 2);

        tot += 1e-7f;
        const float cr   = sr / tot;
        const float ccen = sc / tot;
        const float m    = (float)(KK - 1) * 0.5f;
        const float ang  = atan2f(cr - m, ccen - m + 1e-7f);
        const float c_   = __cosf(ang);
        const float s_   = __sinf(ang);
        const float km1  = (float)(KK - 1);
        co[u] = c_;
        si[u] = s_;
        xo[u] = (km1 - (c_ * km1 - s_ * km1)) * 0.5f;
        yo[u] = (km1 - (s_ * km1 + c_ * km1)) * 0.5f;
    }

    const float scale = 1.0f / (1.0f + 1e-7f);

    float acc[4][4];                    // [ntile][c0..c3]
    #pragma unroll
    for (int nt = 0; nt < 4; nt++)
        #pragma unroll
        for (int k = 0; k < 4; k++) acc[nt][k] = 0.f;

    // --- main loop over 25 target positions ---
    #pragma unroll 1
    for (int j = 0; j < 25; j++) {
        const float gx = (float)(j % KK);
        const float gy = (float)(j / KK);

        uint32_t ra[2][4];              // tf32 rot, [patch u][channel 4q+i]
        #pragma unroll
        for (int u = 0; u < 2; u++) {
            const float sx  = (co[u] * gx - si[u] * gy + xo[u]) * scale;
            const float sy  = (si[u] * gx + co[u] * gy + yo[u]) * scale;
            const float x0f = floorf(sx);
            const float y0f = floorf(sy);
            const float wx  = sx - x0f;
            const float wy  = sy - y0f;
            const int   x0  = (int)x0f;
            const int   y0  = (int)y0f;
            const float tw[4] = { (1.f - wx) * (1.f - wy),
                                  wx * (1.f - wy),
                                  (1.f - wx) * wy,
                                  wx * wy };
            float a0 = 0.f, a1 = 0.f, a2 = 0.f, a3 = 0.f;
            #pragma unroll
            for (int t = 0; t < 4; t++) {
                const int xi = x0 + (t & 1);
                const int yi = y0 + (t >> 1);
                if (xi >= 0 && xi < KK && yi >= 0 && yi < KK) {
                    const float4 v = *reinterpret_cast<const float4*>(
                        pbase[u] + (yi * HDIM + xi) * CCH + q * 4);
                    const float w = tw[t];
                    a0 += w * v.x;
                    a1 += w * v.y;
                    a2 += w * v.z;
                    a3 += w * v.w;
                }
            }
            ra[u][0] = f2tf32(a0);
            ra[u][1] = f2tf32(a1);
            ra[u][2] = f2tf32(a2);
            ra[u][3] = f2tf32(a3);
        }

        // --- 2 k-steps x 4 n-tiles of m16n8k8 ---
        #pragma unroll
        for (int ks = 0; ks < 2; ks++) {
            // A: ks=0 -> channels 4q+0 (col q), 4q+1 (col q+4)
            //    ks=1 -> channels 4q+2, 4q+3
            const uint32_t a0 = ra[0][2 * ks + 0];
            const uint32_t a1 = ra[1][2 * ks + 0];
            const uint32_t a2 = ra[0][2 * ks + 1];
            const uint32_t a3 = ra[1][2 * ks + 1];
            #pragma unroll
            for (int nt = 0; nt < 4; nt++) {
                const uint2 bb = *reinterpret_cast<const uint2*>(
                    smw + ((((j * 2 + ks) * 4 + nt) * 32 + lane) * 2));
                mma_tf32(acc[nt], a0, a1, a2, a3, bb.x, bb.y);
            }
        }
    }

    // --- epilogue: C fragment -> out (+bias), float2 stores ---
    #pragma unroll
    for (int nt = 0; nt < 4; nt++) {
        const float2 bv = *reinterpret_cast<const float2*>(bias + nt * 8 + 2 * q);
        float* o0 = out + (tb + row) * FOUT + nt * 8 + 2 * q;
        float* o1 = out + (tb + row + 8) * FOUT + nt * 8 + 2 * q;
        float2 v0, v1;
        v0.x = acc[nt][0] + bv.x;  v0.y = acc[nt][1] + bv.y;
        v1.x = acc[nt][2] + bv.x;  v1.y = acc[nt][3] + bv.y;
        *reinterpret_cast<float2*>(o0) = v0;
        *reinterpret_cast<float2*>(o1) = v1;
    }
}

extern "C" void kernel_launch(void* const* d_in, const int* in_sizes, int n_in,
                              void* d_out, int out_size)
{
    const float* in   = (const float*)d_in[0];   // [4,128,128,16]
    const float* Wg   = (const float*)d_in[1];   // [32,5,5,16]
    const float* bias = (const float*)d_in[2];   // [32]
    float* out = (float*)d_out;                  // [4,124,124,32]

    const int smem = 25 * 2 * 4 * 32 * 2 * (int)sizeof(uint32_t);   // 51200 B
    cudaFuncSetAttribute(rotconv8_kernel,
                         cudaFuncAttributeMaxDynamicSharedMemorySize, smem);

    const int nblocks = NP / 64;                 // 961 exact
    rotconv8_kernel<<<nblocks, TPB, smem>>>(in, Wg, bias, out);
}

// round 9
// speedup vs baseline: 2.9940x; 1.1176x over previous
#include <cuda_runtime.h>
#include <cuda_bf16.h>
#include <math.h>
#include <cstdint>

// RotationalConv2D v9 — GB300 sm_103a — tf32 mma.sync, branchless taps
// Warp = 16-patch tile; lane t: q=t&3 (channel group), row=t>>2.
// v8 + (1) clamped-index zero-weight taps (no BSSY/BSYNC in hot loop),
//      (2) B-fragments fused to LDS.128 (two n-tiles per load),
//      (3) shared clamp/address computation per tap pair.

#define HDIM 128
#define CCH 16
#define FOUT 32
#define KK 5
#define HO 124
#define WO 124
#define NP (4 * HO * WO)     // 61504 = 961 * 64
#define TPB 128

__device__ __forceinline__ uint32_t f2tf32(float x) {
    uint32_t r;
    asm("cvt.rn.tf32.f32 %0, %1;" : "=r"(r) : "f"(x));
    return r;
}

__device__ __forceinline__ void mma_tf32(float* c,
                                         uint32_t a0, uint32_t a1,
                                         uint32_t a2, uint32_t a3,
                                         uint32_t b0, uint32_t b1) {
    asm volatile(
        "mma.sync.aligned.m16n8k8.row.col.f32.tf32.tf32.f32 "
        "{%0,%1,%2,%3}, {%4,%5,%6,%7}, {%8,%9}, {%0,%1,%2,%3};"
        : "+f"(c[0]), "+f"(c[1]), "+f"(c[2]), "+f"(c[3])
        : "r"(a0), "r"(a1), "r"(a2), "r"(a3), "r"(b0), "r"(b1));
}

__global__ void __launch_bounds__(TPB, 4)
rotconv9_kernel(const float* __restrict__ in,
                const float* __restrict__ Wg,
                const float* __restrict__ bias,
                float* __restrict__ out)
{
    extern __shared__ uint32_t smw[];   // Bfrag[25][2][2][32] x uint4 = 51200 B

    const int tid  = threadIdx.x;
    const int wid  = tid >> 5;
    const int lane = tid & 31;

    // --- stage W as per-lane B fragments, two n-tiles packed per uint4 ---
    // word r2 of [j][ks][ntp][lane]: nt = 2*ntp + (r2>>1), r = r2&1
    // value = W[nt*8 + lane/4][j*16 + 4*(lane%4) + 2*ks + r]
    for (int i = tid; i < 25 * 2 * 2 * 32 * 4; i += TPB) {
        const int r2  = i & 3;
        const int ln  = (i >> 2) & 31;
        const int ntp = (i >> 7) & 1;
        const int ks  = (i >> 8) & 1;
        const int j   = i >> 9;
        const int nt  = 2 * ntp + (r2 >> 1);
        const int r   = r2 & 1;
        smw[i] = f2tf32(Wg[(nt * 8 + (ln >> 2)) * 400 + j * 16 + 4 * (ln & 3) + 2 * ks + r]);
    }
    __syncthreads();

    const int q   = lane & 3;
    const int row = lane >> 2;
    const int tb  = blockIdx.x * 64 + wid * 16;   // exact grid, no tail

    const float* pbase[2];
    float co[2], si[2], xo[2], yo[2];

    #pragma unroll
    for (int u = 0; u < 2; u++) {
        const int P   = tb + row + 8 * u;
        const int b   = P / (HO * WO);
        const int rem = P - b * (HO * WO);
        const int ho  = rem / WO;
        const int wo  = rem - ho * WO;
        const float* pb = in + ((b * HDIM + ho) * HDIM + wo) * CCH + q * 4;
        pbase[u] = pb;

        float tot = 0.f, sr = 0.f, sc = 0.f;
        #pragma unroll
        for (int r = 0; r < KK; r++) {
            #pragma unroll
            for (int cl = 0; cl < KK; cl++) {
                float4 v = *reinterpret_cast<const float4*>(pb + (r * HDIM + cl) * CCH);
                float s = v.x + v.y + v.z + v.w;
                tot += s;
                sr  += s * (float)r;
                sc  += s * (float)cl;
            }
        }
        tot += __shfl_xor_sync(0xffffffffu, tot, 1);
        tot += __shfl_xor_sync(0xffffffffu, tot, 2);
        sr  += __shfl_xor_sync(0xffffffffu, sr, 1);
        sr  += __shfl_xor_sync(0xffffffffu, sr, 2);
        sc  += __shfl_xor_sync(0xffffffffu, sc, 1);
        sc  += __shfl_xor_sync(0xffffffffu, sc, 2);

        tot += 1e-7f;
        const float cr   = sr / tot;
        const float ccen = sc / tot;
        const float m    = (float)(KK - 1) * 0.5f;
        const float ang  = atan2f(cr - m, ccen - m + 1e-7f);
        const float c_   = __cosf(ang);
        const float s_   = __sinf(ang);
        const float km1  = (float)(KK - 1);
        co[u] = c_;
        si[u] = s_;
        xo[u] = (km1 - (c_ * km1 - s_ * km1)) * 0.5f;
        yo[u] = (km1 - (s_ * km1 + c_ * km1)) * 0.5f;
    }

    const float scale = 1.0f / (1.0f + 1e-7f);

    float acc[4][4];
    #pragma unroll
    for (int nt = 0; nt < 4; nt++)
        #pragma unroll
        for (int k = 0; k < 4; k++) acc[nt][k] = 0.f;

    // --- main loop over 25 target positions ---
    int j = 0;
    #pragma unroll 1
    for (int jy = 0; jy < KK; jy++) {
        #pragma unroll 1
        for (int jx = 0; jx < KK; jx++, j++) {
            const float gx = (float)jx;
            const float gy = (float)jy;

            // B fragments first: LDS latency overlaps the tap LDGs below
            const uint4* bp = reinterpret_cast<const uint4*>(smw) + (j * 4) * 32 + lane;
            const uint4 bk0a = bp[0];        // ks=0, nt 0|1
            const uint4 bk0b = bp[32];       // ks=0, nt 2|3
            const uint4 bk1a = bp[64];       // ks=1, nt 0|1
            const uint4 bk1b = bp[96];       // ks=1, nt 2|3

            uint32_t ra[2][4];
            #pragma unroll
            for (int u = 0; u < 2; u++) {
                const float sx  = (co[u] * gx - si[u] * gy + xo[u]) * scale;
                const float sy  = (si[u] * gx + co[u] * gy + yo[u]) * scale;
                const float x0f = floorf(sx);
                const float y0f = floorf(sy);
                const float wx  = sx - x0f;
                const float wy  = sy - y0f;
                const int   x0  = (int)x0f;
                const int   y0  = (int)y0f;
                const int   x1  = x0 + 1;
                const int   y1  = y0 + 1;

                // branchless: clamp indices, zero weights when out of range
                const bool vx0 = (unsigned)x0 < KK;   // x0>=0 && x0<5
                const bool vx1 = (unsigned)x1 < KK;
                const bool vy0 = (unsigned)y0 < KK;
                const bool vy1 = (unsigned)y1 < KK;
                const int x0c = min(max(x0, 0), KK - 1);
                const int x1c = min(max(x1, 0), KK - 1);
                const int y0c = min(max(y0, 0), KK - 1);
                const int y1c = min(max(y1, 0), KK - 1);

                const float wx1 = 1.f - wx;
                const float wy1 = 1.f - wy;
                const float w00 = (vx0 && vy0) ? wx1 * wy1 : 0.f;
                const float w01 = (vx1 && vy0) ? wx  * wy1 : 0.f;
                const float w10 = (vx0 && vy1) ? wx1 * wy  : 0.f;
                const float w11 = (vx1 && vy1) ? wx  * wy  : 0.f;

                const float* r0 = pbase[u] + y0c * (HDIM * CCH);
                const float* r1 = pbase[u] + y1c * (HDIM * CCH);
                const float4 v00 = *reinterpret_cast<const float4*>(r0 + x0c * CCH);
                const float4 v01 = *reinterpret_cast<const float4*>(r0 + x1c * CCH);
                const float4 v10 = *reinterpret_cast<const float4*>(r1 + x0c * CCH);
                const float4 v11 = *reinterpret_cast<const float4*>(r1 + x1c * CCH);

                const float a0 = w00 * v00.x + w01 * v01.x + w10 * v10.x + w11 * v11.x;
                const float a1 = w00 * v00.y + w01 * v01.y + w10 * v10.y + w11 * v11.y;
                const float a2 = w00 * v00.z + w01 * v01.z + w10 * v10.z + w11 * v11.z;
                const float a3 = w00 * v00.w + w01 * v01.w + w10 * v10.w + w11 * v11.w;

                ra[u][0] = f2tf32(a0);
                ra[u][1] = f2tf32(a1);
                ra[u][2] = f2tf32(a2);
                ra[u][3] = f2tf32(a3);
            }

            // ks=0: channels 4q+0 (k-col q), 4q+1 (k-col q+4)
            mma_tf32(acc[0], ra[0][0], ra[1][0], ra[0][1], ra[1][1], bk0a.x, bk0a.y);
            mma_tf32(acc[1], ra[0][0], ra[1][0], ra[0][1], ra[1][1], bk0a.z, bk0a.w);
            mma_tf32(acc[2], ra[0][0], ra[1][0], ra[0][1], ra[1][1], bk0b.x, bk0b.y);
            mma_tf32(acc[3], ra[0][0], ra[1][0], ra[0][1], ra[1][1], bk0b.z, bk0b.w);
            // ks=1: channels 4q+2, 4q+3
            mma_tf32(acc[0], ra[0][2], ra[1][2], ra[0][3], ra[1][3], bk1a.x, bk1a.y);
            mma_tf32(acc[1], ra[0][2], ra[1][2], ra[0][3], ra[1][3], bk1a.z, bk1a.w);
            mma_tf32(acc[2], ra[0][2], ra[1][2], ra[0][3], ra[1][3], bk1b.x, bk1b.y);
            mma_tf32(acc[3], ra[0][2], ra[1][2], ra[0][3], ra[1][3], bk1b.z, bk1b.w);
        }
    }

    // --- epilogue: C fragment -> out (+bias) ---
    #pragma unroll
    for (int nt = 0; nt < 4; nt++) {
        const float2 bv = *reinterpret_cast<const float2*>(bias + nt * 8 + 2 * q);
        float* o0 = out + (tb + row) * FOUT + nt * 8 + 2 * q;
        float* o1 = out + (tb + row + 8) * FOUT + nt * 8 + 2 * q;
        float2 v0, v1;
        v0.x = acc[nt][0] + bv.x;  v0.y = acc[nt][1] + bv.y;
        v1.x = acc[nt][2] + bv.x;  v1.y = acc[nt][3] + bv.y;
        *reinterpret_cast<float2*>(o0) = v0;
        *reinterpret_cast<float2*>(o1) = v1;
    }
}

extern "C" void kernel_launch(void* const* d_in, const int* in_sizes, int n_in,
                              void* d_out, int out_size)
{
    const float* in   = (const float*)d_in[0];   // [4,128,128,16]
    const float* Wg   = (const float*)d_in[1];   // [32,5,5,16]
    const float* bias = (const float*)d_in[2];   // [32]
    float* out = (float*)d_out;                  // [4,124,124,32]

    const int smem = 25 * 2 * 2 * 32 * 4 * (int)sizeof(uint32_t);   // 51200 B
    cudaFuncSetAttribute(rotconv9_kernel,
                         cudaFuncAttributeMaxDynamicSharedMemorySize, smem);

    const int nblocks = NP / 64;                 // 961 exact
    rotconv9_kernel<<<nblocks, TPB, smem>>>(in, Wg, bias, out);
}